// round 8
// baseline (speedup 1.0000x reference)
#include <cuda_runtime.h>
#include <cuda_fp16.h>
#include <cstdint>

// Problem dims (fixed)
#define NN   8192
#define DIN  4096
#define DOUT 4096
#define RK   256

// ---------------------------------------------------------------------------
// Device scratch. Referenced ONLY from device code (host-passing __device__
// globals was the R6 failure).
// ---------------------------------------------------------------------------
__device__ __align__(256) __half g_x16[(size_t)NN * DIN];     // 64 MB
__device__ __align__(256) __half g_w16[(size_t)DOUT * DIN];   // 32 MB
__device__ __align__(256) __half g_bb16[(size_t)DOUT * RK];   // 2 MB  (b[o]*B[o][r])
__device__ __align__(256) __half g_adt16[(size_t)DIN * RK];   // 2 MB  (d[r]*A[r][i], transposed)

// ---------------------------------------------------------------------------
// PTX helpers (baseline ISA only)
// ---------------------------------------------------------------------------
__device__ __forceinline__ uint32_t smem_u32(const void* p) {
    uint32_t a;
    asm("{ .reg .u64 t; cvta.to.shared.u64 t, %1; cvt.u32.u64 %0, t; }" : "=r"(a) : "l"(p));
    return a;
}

#define CP_ASYNC16(dst, src) \
    asm volatile("cp.async.cg.shared.global [%0], [%1], 16;" :: "r"(dst), "l"(src) : "memory")
#define CP_ASYNC_COMMIT() asm volatile("cp.async.commit_group;" ::: "memory")
#define CP_ASYNC_WAIT(n)  asm volatile("cp.async.wait_group %0;" :: "n"(n) : "memory")

__device__ __forceinline__ void ldmatrix_x4(uint32_t* r, uint32_t addr) {
    asm volatile("ldmatrix.sync.aligned.m8n8.x4.shared.b16 {%0,%1,%2,%3}, [%4];"
                 : "=r"(r[0]), "=r"(r[1]), "=r"(r[2]), "=r"(r[3]) : "r"(addr));
}

__device__ __forceinline__ void mma16816(float* c, const uint32_t* a, const uint32_t* b) {
    asm volatile(
        "mma.sync.aligned.m16n8k16.row.col.f32.f16.f16.f32 "
        "{%0,%1,%2,%3}, {%4,%5,%6,%7}, {%8,%9}, {%0,%1,%2,%3};"
        : "+f"(c[0]), "+f"(c[1]), "+f"(c[2]), "+f"(c[3])
        : "r"(a[0]), "r"(a[1]), "r"(a[2]), "r"(a[3]), "r"(b[0]), "r"(b[1]));
}

__device__ __forceinline__ uint32_t swz(uint32_t off) {   // SW128
    return off ^ ((off >> 3) & 0x70);
}

// ---------------------------------------------------------------------------
// Conversion kernels
// ---------------------------------------------------------------------------
__global__ __launch_bounds__(256)
void conv_x_kernel(const float* __restrict__ x) {
    size_t i = ((size_t)blockIdx.x * blockDim.x + threadIdx.x) * 8;
    float4 a = *reinterpret_cast<const float4*>(x + i);
    float4 b = *reinterpret_cast<const float4*>(x + i + 4);
    float v[8] = {a.x, a.y, a.z, a.w, b.x, b.y, b.z, b.w};
    __align__(16) __half h[8];
    #pragma unroll
    for (int j = 0; j < 8; j++) h[j] = __float2half_rn(v[j]);
    *reinterpret_cast<uint4*>(&g_x16[i]) = *reinterpret_cast<uint4*>(h);
}

__global__ __launch_bounds__(256)
void conv_b_kernel(const float* __restrict__ Bm, const float* __restrict__ bvec) {
    size_t i = ((size_t)blockIdx.x * blockDim.x + threadIdx.x) * 8;
    const int o = (int)(i / RK);
    const float s = bvec[o];
    float4 a = *reinterpret_cast<const float4*>(Bm + i);
    float4 b = *reinterpret_cast<const float4*>(Bm + i + 4);
    float v[8] = {a.x, a.y, a.z, a.w, b.x, b.y, b.z, b.w};
    __align__(16) __half h[8];
    #pragma unroll
    for (int j = 0; j < 8; j++) h[j] = __float2half_rn(v[j] * s);
    *reinterpret_cast<uint4*>(&g_bb16[i]) = *reinterpret_cast<uint4*>(h);
}

__global__ __launch_bounds__(256)
void conv_adt_kernel(const float* __restrict__ A, const float* __restrict__ dvec) {
    __shared__ float tile[32][33];
    const int r0 = blockIdx.y * 32;
    const int i0 = blockIdx.x * 32;
    const int tx = threadIdx.x & 31;
    const int ty = threadIdx.x >> 5;
    #pragma unroll
    for (int t = 0; t < 4; t++) {
        const int r = ty + t * 8;
        tile[r][tx] = A[(size_t)(r0 + r) * DIN + i0 + tx] * dvec[r0 + r];
    }
    __syncthreads();
    #pragma unroll
    for (int t = 0; t < 4; t++) {
        const int i = ty + t * 8;
        g_adt16[(size_t)(i0 + i) * RK + r0 + tx] = __float2half_rn(tile[tx][i]);
    }
}

// ---------------------------------------------------------------------------
// NT-GEMM via mma.sync fp16. 1024 threads (32 warps), warp tile 32x32,
// CTA tile 128x256, KC=64 (128 B rows, SW128), NSTAGE=4, single sync/iter.
//   FOLD=false: out[m][n] = sum_k x16[m][k]*w16[n][k] + bias[n]   (f32 out)
//   FOLD=true : w16[m][n] = fp16(W[m][n] + sum_k bb16[m][k]*adt16[n][k])
// ---------------------------------------------------------------------------
#define BM 128
#define BN 256
#define KC 64
#define A_BYTES (BM * 128)              // 16384
#define B_BYTES (BN * 128)              // 32768
#define STAGE_BYTES (A_BYTES + B_BYTES) // 49152
#define NSTAGE 4
#define SMEM_TOTAL (NSTAGE * STAGE_BYTES)  // 196608
#define NTHREADS 1024

template<bool FOLD>
__device__ __forceinline__ void load_chunk(int chunk, uint32_t st, int tid,
                                           int m0, int n0) {
    const int KSTRIDE = FOLD ? RK : DIN;
    const __half* __restrict__ Aop = FOLD ? g_bb16 : g_x16;
    const __half* __restrict__ Bop = FOLD ? g_adt16 : g_w16;

    const int koff = chunk * KC;
    const int seg = tid & 7;        // 16B segment within 128B row
    const int rb  = tid >> 3;       // 0..127
    {   // A: 128 rows, 1 op/thread
        const __half* g = Aop + (size_t)(m0 + rb) * KSTRIDE + koff + seg * 8;
        uint32_t off = rb * 128 + seg * 16;
        CP_ASYNC16(st + swz(off), g);
    }
    #pragma unroll
    for (int t = 0; t < 2; t++) {   // B: 256 rows, 2 ops/thread
        const int r = t * 128 + rb;
        const __half* g = Bop + (size_t)(n0 + r) * KSTRIDE + koff + seg * 8;
        uint32_t off = r * 128 + seg * 16;
        CP_ASYNC16(st + A_BYTES + swz(off), g);
    }
}

template<bool FOLD>
__global__ __launch_bounds__(NTHREADS, 1)
void gemm_tpl(const float* __restrict__ aux,   // bias (FOLD=0) or W (FOLD=1)
              float* __restrict__ outf) {      // main output (FOLD=0 only)
    const int NCHUNK = FOLD ? (RK / KC) : (DIN / KC);

    extern __shared__ char smem[];
    const uint32_t sb = smem_u32(smem);
    const int tid  = threadIdx.x;
    const int lane = tid & 31;
    const int wid  = tid >> 5;          // 0..31
    const int warp_m = wid & 3;         // 0..3 -> 32-row slab
    const int warp_n = wid >> 2;        // 0..7 -> 32-col slab

    const int n0 = blockIdx.x * BN;
    const int m0 = blockIdx.y * BM;

    float acc[2][4][4] = {};            // [mt][nt][4], warp tile 32x32

    const int arow = lane & 15;
    const int acol = (lane >> 4) * 8;
    const int brow = (lane & 7) + ((lane >> 4) << 3);
    const int bcol = ((lane >> 3) & 1) * 8;

    // Prologue: stages 0..2
    load_chunk<FOLD>(0, sb, tid, m0, n0);
    CP_ASYNC_COMMIT();
    load_chunk<FOLD>(1, sb + STAGE_BYTES, tid, m0, n0);
    CP_ASYNC_COMMIT();
    load_chunk<FOLD>(2, sb + 2 * STAGE_BYTES, tid, m0, n0);
    CP_ASYNC_COMMIT();

    for (int i = 0; i < NCHUNK; i++) {
        const uint32_t st = sb + (i % NSTAGE) * STAGE_BYTES;

        if (i < NCHUNK - 2)       { CP_ASYNC_WAIT(2); }
        else if (i == NCHUNK - 2) { CP_ASYNC_WAIT(1); }
        else                      { CP_ASYNC_WAIT(0); }
        // Single barrier: publishes stage i AND protects stage (i-1)%4,
        // which is exactly the stage the prefetch below overwrites.
        __syncthreads();

        if (i + 3 < NCHUNK) {
            load_chunk<FOLD>(i + 3, sb + ((i + 3) % NSTAGE) * STAGE_BYTES,
                             tid, m0, n0);
            CP_ASYNC_COMMIT();
        }

        #pragma unroll
        for (int ks = 0; ks < 4; ks++) {
            uint32_t a[2][4];
            #pragma unroll
            for (int mt = 0; mt < 2; mt++) {
                uint32_t off = (uint32_t)(warp_m * 32 + mt * 16 + arow) * 128
                             + (ks * 16 + acol) * 2;
                ldmatrix_x4(a[mt], st + swz(off));
            }
            uint32_t b[4][2];
            #pragma unroll
            for (int bg = 0; bg < 2; bg++) {
                uint32_t r[4];
                uint32_t off = (uint32_t)(warp_n * 32 + bg * 16 + brow) * 128
                             + (ks * 16 + bcol) * 2;
                ldmatrix_x4(r, st + A_BYTES + swz(off));
                b[bg * 2 + 0][0] = r[0]; b[bg * 2 + 0][1] = r[1];
                b[bg * 2 + 1][0] = r[2]; b[bg * 2 + 1][1] = r[3];
            }
            #pragma unroll
            for (int mt = 0; mt < 2; mt++)
                #pragma unroll
                for (int nt = 0; nt < 4; nt++)
                    mma16816(acc[mt][nt], a[mt], b[nt]);
        }
    }
    __syncthreads();   // protect smem before any future reuse / exit ordering

    // Epilogue
    const int r0 = m0 + warp_m * 32 + (lane >> 2);
    const int c0 = n0 + warp_n * 32 + (lane & 3) * 2;
    #pragma unroll
    for (int mt = 0; mt < 2; mt++) {
        const int rm = r0 + mt * 16;
        #pragma unroll
        for (int nt = 0; nt < 4; nt++) {
            const int cb = c0 + nt * 8;
            if (FOLD) {
                const float2 w0 = *reinterpret_cast<const float2*>(&aux[(size_t)rm * DIN + cb]);
                const float2 w1 = *reinterpret_cast<const float2*>(&aux[(size_t)(rm + 8) * DIN + cb]);
                __half2 h0, h1;
                h0.x = __float2half_rn(w0.x + acc[mt][nt][0]);
                h0.y = __float2half_rn(w0.y + acc[mt][nt][1]);
                h1.x = __float2half_rn(w1.x + acc[mt][nt][2]);
                h1.y = __float2half_rn(w1.y + acc[mt][nt][3]);
                *reinterpret_cast<__half2*>(&g_w16[(size_t)rm * DIN + cb]) = h0;
                *reinterpret_cast<__half2*>(&g_w16[(size_t)(rm + 8) * DIN + cb]) = h1;
            } else {
                const float2 bb = *reinterpret_cast<const float2*>(&aux[cb]);
                float2 v0, v1;
                v0.x = acc[mt][nt][0] + bb.x;
                v0.y = acc[mt][nt][1] + bb.y;
                v1.x = acc[mt][nt][2] + bb.x;
                v1.y = acc[mt][nt][3] + bb.y;
                *reinterpret_cast<float2*>(&outf[(size_t)rm * DOUT + cb]) = v0;
                *reinterpret_cast<float2*>(&outf[(size_t)(rm + 8) * DOUT + cb]) = v1;
            }
        }
    }
}

// ---------------------------------------------------------------------------
// Harness entry. Inputs: x, W, bias, A_frozen, B_frozen, b_vec, d_vec.
// ---------------------------------------------------------------------------
extern "C" void kernel_launch(void* const* d_in, const int* in_sizes, int n_in,
                              void* d_out, int out_size) {
    const float* x    = (const float*)d_in[0];
    const float* W    = (const float*)d_in[1];
    const float* bias = (const float*)d_in[2];
    const float* A    = (const float*)d_in[3];
    const float* Bm   = (const float*)d_in[4];
    const float* bvec = (const float*)d_in[5];
    const float* dvec = (const float*)d_in[6];
    float* out = (float*)d_out;

    static int attr_set = 0;
    if (!attr_set) {
        cudaFuncSetAttribute(gemm_tpl<false>,
                             cudaFuncAttributeMaxDynamicSharedMemorySize, SMEM_TOTAL);
        cudaFuncSetAttribute(gemm_tpl<true>,
                             cudaFuncAttributeMaxDynamicSharedMemorySize, SMEM_TOTAL);
        attr_set = 1;
    }

    // fp16 conversions
    conv_x_kernel<<<(unsigned)((size_t)NN * DIN / 8 / 256), 256>>>(x);
    conv_b_kernel<<<(unsigned)((size_t)DOUT * RK / 8 / 256), 256>>>(Bm, bvec);
    {
        dim3 grid(DIN / 32, RK / 32);
        conv_adt_kernel<<<grid, 256>>>(A, dvec);
    }

    // Fold: w16 = fp16(W + bb16 @ adt16^T), K = RK
    {
        dim3 grid(DIN / BN, DOUT / BM);     // 16 x 32
        gemm_tpl<true><<<grid, NTHREADS, SMEM_TOTAL>>>(W, nullptr);
    }
    // Main GEMM: out = x16 @ w16^T + bias, K = DIN
    {
        dim3 grid(DOUT / BN, NN / BM);      // 16 x 64
        gemm_tpl<false><<<grid, NTHREADS, SMEM_TOTAL>>>(bias, out);
    }
}

// round 9
// speedup vs baseline: 1.2088x; 1.2088x over previous
#include <cuda_runtime.h>
#include <cuda_fp16.h>
#include <cstdint>

// Problem dims (fixed)
#define NN   8192
#define DIN  4096
#define DOUT 4096
#define RK   256

// ---------------------------------------------------------------------------
// Device scratch. Referenced ONLY from device code (host-passing __device__
// globals was the R6 failure).
// ---------------------------------------------------------------------------
__device__ __align__(256) __half g_x16[(size_t)NN * DIN];     // 64 MB
__device__ __align__(256) __half g_w16[(size_t)DOUT * DIN];   // 32 MB
__device__ __align__(256) __half g_bb16[(size_t)DOUT * RK];   // 2 MB  (b[o]*B[o][r])
__device__ __align__(256) __half g_adt16[(size_t)DIN * RK];   // 2 MB  (d[r]*A[r][i], transposed)

// ---------------------------------------------------------------------------
// PTX helpers (baseline ISA only)
// ---------------------------------------------------------------------------
__device__ __forceinline__ uint32_t smem_u32(const void* p) {
    uint32_t a;
    asm("{ .reg .u64 t; cvta.to.shared.u64 t, %1; cvt.u32.u64 %0, t; }" : "=r"(a) : "l"(p));
    return a;
}

#define CP_ASYNC16(dst, src) \
    asm volatile("cp.async.cg.shared.global [%0], [%1], 16;" :: "r"(dst), "l"(src) : "memory")
#define CP_ASYNC_COMMIT() asm volatile("cp.async.commit_group;" ::: "memory")
#define CP_ASYNC_WAIT(n)  asm volatile("cp.async.wait_group %0;" :: "n"(n) : "memory")

__device__ __forceinline__ void ldmatrix_x4(uint32_t* r, uint32_t addr) {
    asm volatile("ldmatrix.sync.aligned.m8n8.x4.shared.b16 {%0,%1,%2,%3}, [%4];"
                 : "=r"(r[0]), "=r"(r[1]), "=r"(r[2]), "=r"(r[3]) : "r"(addr));
}

__device__ __forceinline__ void mma16816(float* c, const uint32_t* a, const uint32_t* b) {
    asm volatile(
        "mma.sync.aligned.m16n8k16.row.col.f32.f16.f16.f32 "
        "{%0,%1,%2,%3}, {%4,%5,%6,%7}, {%8,%9}, {%0,%1,%2,%3};"
        : "+f"(c[0]), "+f"(c[1]), "+f"(c[2]), "+f"(c[3])
        : "r"(a[0]), "r"(a[1]), "r"(a[2]), "r"(a[3]), "r"(b[0]), "r"(b[1]));
}

__device__ __forceinline__ uint32_t swz(uint32_t off) {   // SW128
    return off ^ ((off >> 3) & 0x70);
}

// ---------------------------------------------------------------------------
// Conversion kernels
// ---------------------------------------------------------------------------
__global__ __launch_bounds__(256)
void conv_x_kernel(const float* __restrict__ x) {
    size_t i = ((size_t)blockIdx.x * blockDim.x + threadIdx.x) * 8;
    float4 a = *reinterpret_cast<const float4*>(x + i);
    float4 b = *reinterpret_cast<const float4*>(x + i + 4);
    float v[8] = {a.x, a.y, a.z, a.w, b.x, b.y, b.z, b.w};
    __align__(16) __half h[8];
    #pragma unroll
    for (int j = 0; j < 8; j++) h[j] = __float2half_rn(v[j]);
    *reinterpret_cast<uint4*>(&g_x16[i]) = *reinterpret_cast<uint4*>(h);
}

__global__ __launch_bounds__(256)
void conv_b_kernel(const float* __restrict__ Bm, const float* __restrict__ bvec) {
    size_t i = ((size_t)blockIdx.x * blockDim.x + threadIdx.x) * 8;
    const int o = (int)(i / RK);
    const float s = bvec[o];
    float4 a = *reinterpret_cast<const float4*>(Bm + i);
    float4 b = *reinterpret_cast<const float4*>(Bm + i + 4);
    float v[8] = {a.x, a.y, a.z, a.w, b.x, b.y, b.z, b.w};
    __align__(16) __half h[8];
    #pragma unroll
    for (int j = 0; j < 8; j++) h[j] = __float2half_rn(v[j] * s);
    *reinterpret_cast<uint4*>(&g_bb16[i]) = *reinterpret_cast<uint4*>(h);
}

__global__ __launch_bounds__(256)
void conv_adt_kernel(const float* __restrict__ A, const float* __restrict__ dvec) {
    __shared__ float tile[32][33];
    const int r0 = blockIdx.y * 32;
    const int i0 = blockIdx.x * 32;
    const int tx = threadIdx.x & 31;
    const int ty = threadIdx.x >> 5;
    #pragma unroll
    for (int t = 0; t < 4; t++) {
        const int r = ty + t * 8;
        tile[r][tx] = A[(size_t)(r0 + r) * DIN + i0 + tx] * dvec[r0 + r];
    }
    __syncthreads();
    #pragma unroll
    for (int t = 0; t < 4; t++) {
        const int i = ty + t * 8;
        g_adt16[(size_t)(i0 + i) * RK + r0 + tx] = __float2half_rn(tile[tx][i]);
    }
}

// ---------------------------------------------------------------------------
// NT-GEMM via mma.sync fp16. 512 threads (16 warps), warp tile 64x32,
// CTA tile 128x256, KC=64 (128 B rows, SW128), NSTAGE=4, ONE sync per iter.
//   FOLD=false: out[m][n] = sum_k x16[m][k]*w16[n][k] + bias[n]   (f32 out)
//   FOLD=true : w16[m][n] = fp16(W[m][n] + sum_k bb16[m][k]*adt16[n][k])
// ---------------------------------------------------------------------------
#define BM 128
#define BN 256
#define KC 64
#define A_BYTES (BM * 128)              // 16384
#define B_BYTES (BN * 128)              // 32768
#define STAGE_BYTES (A_BYTES + B_BYTES) // 49152
#define NSTAGE 4
#define SMEM_TOTAL (NSTAGE * STAGE_BYTES)  // 196608
#define NTHREADS 512

template<bool FOLD>
__device__ __forceinline__ void load_chunk(int chunk, uint32_t st, int tid,
                                           int m0, int n0) {
    const int KSTRIDE = FOLD ? RK : DIN;
    const __half* __restrict__ Aop = FOLD ? g_bb16 : g_x16;
    const __half* __restrict__ Bop = FOLD ? g_adt16 : g_w16;

    const int koff = chunk * KC;
    const int seg = tid & 7;        // 16B segment within 128B row
    const int rb  = tid >> 3;       // 0..63
    #pragma unroll
    for (int t = 0; t < 2; t++) {   // A: 128 rows
        const int r = t * 64 + rb;
        const __half* g = Aop + (size_t)(m0 + r) * KSTRIDE + koff + seg * 8;
        uint32_t off = r * 128 + seg * 16;
        CP_ASYNC16(st + swz(off), g);
    }
    #pragma unroll
    for (int t = 0; t < 4; t++) {   // B: 256 rows
        const int r = t * 64 + rb;
        const __half* g = Bop + (size_t)(n0 + r) * KSTRIDE + koff + seg * 8;
        uint32_t off = r * 128 + seg * 16;
        CP_ASYNC16(st + A_BYTES + swz(off), g);
    }
}

template<bool FOLD>
__global__ __launch_bounds__(NTHREADS, 1)
void gemm_tpl(const float* __restrict__ aux,   // bias (FOLD=0) or W (FOLD=1)
              float* __restrict__ outf) {      // main output (FOLD=0 only)
    const int NCHUNK = FOLD ? (RK / KC) : (DIN / KC);

    extern __shared__ char smem[];
    const uint32_t sb = smem_u32(smem);
    const int tid  = threadIdx.x;
    const int lane = tid & 31;
    const int wid  = tid >> 5;          // 0..15
    const int warp_m = wid & 1;         // 0..1  -> 64-row slab
    const int warp_n = wid >> 1;        // 0..7  -> 32-col slab

    const int n0 = blockIdx.x * BN;
    const int m0 = blockIdx.y * BM;

    float acc[4][4][4] = {};            // [mt][nt][4], warp tile 64x32

    const int arow = lane & 15;
    const int acol = (lane >> 4) * 8;
    const int brow = (lane & 7) + ((lane >> 4) << 3);
    const int bcol = ((lane >> 3) & 1) * 8;

    // Prologue: stages 0..2
    load_chunk<FOLD>(0, sb, tid, m0, n0);
    CP_ASYNC_COMMIT();
    load_chunk<FOLD>(1, sb + STAGE_BYTES, tid, m0, n0);
    CP_ASYNC_COMMIT();
    load_chunk<FOLD>(2, sb + 2 * STAGE_BYTES, tid, m0, n0);
    CP_ASYNC_COMMIT();

    for (int i = 0; i < NCHUNK; i++) {
        const uint32_t st = sb + (i % NSTAGE) * STAGE_BYTES;

        if (i < NCHUNK - 2)       { CP_ASYNC_WAIT(2); }
        else if (i == NCHUNK - 2) { CP_ASYNC_WAIT(1); }
        else                      { CP_ASYNC_WAIT(0); }
        // Single barrier: publishes stage i to all warps AND guarantees every
        // warp finished computing stage (i-1)%4 — exactly the stage the
        // prefetch below overwrites. No trailing barrier needed.
        __syncthreads();

        if (i + 3 < NCHUNK) {
            load_chunk<FOLD>(i + 3, sb + ((i + 3) % NSTAGE) * STAGE_BYTES,
                             tid, m0, n0);
            CP_ASYNC_COMMIT();
        }

        #pragma unroll
        for (int ks = 0; ks < 4; ks++) {
            uint32_t a[4][4];
            #pragma unroll
            for (int mt = 0; mt < 4; mt++) {
                uint32_t off = (uint32_t)(warp_m * 64 + mt * 16 + arow) * 128
                             + (ks * 16 + acol) * 2;
                ldmatrix_x4(a[mt], st + swz(off));
            }
            uint32_t b[4][2];
            #pragma unroll
            for (int bg = 0; bg < 2; bg++) {
                uint32_t r[4];
                uint32_t off = (uint32_t)(warp_n * 32 + bg * 16 + brow) * 128
                             + (ks * 16 + bcol) * 2;
                ldmatrix_x4(r, st + A_BYTES + swz(off));
                b[bg * 2 + 0][0] = r[0]; b[bg * 2 + 0][1] = r[1];
                b[bg * 2 + 1][0] = r[2]; b[bg * 2 + 1][1] = r[3];
            }
            #pragma unroll
            for (int mt = 0; mt < 4; mt++)
                #pragma unroll
                for (int nt = 0; nt < 4; nt++)
                    mma16816(acc[mt][nt], a[mt], b[nt]);
        }
    }

    // Epilogue
    const int r0 = m0 + warp_m * 64 + (lane >> 2);
    const int c0 = n0 + warp_n * 32 + (lane & 3) * 2;
    #pragma unroll
    for (int mt = 0; mt < 4; mt++) {
        const int rm = r0 + mt * 16;
        #pragma unroll
        for (int nt = 0; nt < 4; nt++) {
            const int cb = c0 + nt * 8;
            if (FOLD) {
                const float2 w0 = *reinterpret_cast<const float2*>(&aux[(size_t)rm * DIN + cb]);
                const float2 w1 = *reinterpret_cast<const float2*>(&aux[(size_t)(rm + 8) * DIN + cb]);
                __half2 h0, h1;
                h0.x = __float2half_rn(w0.x + acc[mt][nt][0]);
                h0.y = __float2half_rn(w0.y + acc[mt][nt][1]);
                h1.x = __float2half_rn(w1.x + acc[mt][nt][2]);
                h1.y = __float2half_rn(w1.y + acc[mt][nt][3]);
                *reinterpret_cast<__half2*>(&g_w16[(size_t)rm * DIN + cb]) = h0;
                *reinterpret_cast<__half2*>(&g_w16[(size_t)(rm + 8) * DIN + cb]) = h1;
            } else {
                const float2 bb = *reinterpret_cast<const float2*>(&aux[cb]);
                float2 v0, v1;
                v0.x = acc[mt][nt][0] + bb.x;
                v0.y = acc[mt][nt][1] + bb.y;
                v1.x = acc[mt][nt][2] + bb.x;
                v1.y = acc[mt][nt][3] + bb.y;
                *reinterpret_cast<float2*>(&outf[(size_t)rm * DOUT + cb]) = v0;
                *reinterpret_cast<float2*>(&outf[(size_t)(rm + 8) * DOUT + cb]) = v1;
            }
        }
    }
}

// ---------------------------------------------------------------------------
// Harness entry. Inputs: x, W, bias, A_frozen, B_frozen, b_vec, d_vec.
// ---------------------------------------------------------------------------
extern "C" void kernel_launch(void* const* d_in, const int* in_sizes, int n_in,
                              void* d_out, int out_size) {
    const float* x    = (const float*)d_in[0];
    const float* W    = (const float*)d_in[1];
    const float* bias = (const float*)d_in[2];
    const float* A    = (const float*)d_in[3];
    const float* Bm   = (const float*)d_in[4];
    const float* bvec = (const float*)d_in[5];
    const float* dvec = (const float*)d_in[6];
    float* out = (float*)d_out;

    static int attr_set = 0;
    if (!attr_set) {
        cudaFuncSetAttribute(gemm_tpl<false>,
                             cudaFuncAttributeMaxDynamicSharedMemorySize, SMEM_TOTAL);
        cudaFuncSetAttribute(gemm_tpl<true>,
                             cudaFuncAttributeMaxDynamicSharedMemorySize, SMEM_TOTAL);
        attr_set = 1;
    }

    // fp16 conversions
    conv_x_kernel<<<(unsigned)((size_t)NN * DIN / 8 / 256), 256>>>(x);
    conv_b_kernel<<<(unsigned)((size_t)DOUT * RK / 8 / 256), 256>>>(Bm, bvec);
    {
        dim3 grid(DIN / 32, RK / 32);
        conv_adt_kernel<<<grid, 256>>>(A, dvec);
    }

    // Fold: w16 = fp16(W + bb16 @ adt16^T), K = RK
    {
        dim3 grid(DIN / BN, DOUT / BM);     // 16 x 32
        gemm_tpl<true><<<grid, NTHREADS, SMEM_TOTAL>>>(W, nullptr);
    }
    // Main GEMM: out = x16 @ w16^T + bias, K = DIN
    {
        dim3 grid(DOUT / BN, NN / BM);      // 16 x 64
        gemm_tpl<false><<<grid, NTHREADS, SMEM_TOTAL>>>(bias, out);
    }
}

// round 10
// speedup vs baseline: 1.2969x; 1.0729x over previous
#include <cuda_runtime.h>
#include <cuda_fp16.h>
#include <cstdint>

// Problem dims (fixed)
#define NN   8192
#define DIN  4096
#define DOUT 4096
#define RK   256

// ---------------------------------------------------------------------------
// Device scratch. Referenced ONLY from device code.
// ---------------------------------------------------------------------------
__device__ __align__(256) __half g_x16[(size_t)NN * DIN];     // 64 MB
__device__ __align__(256) __half g_w16[(size_t)DOUT * DIN];   // 32 MB
__device__ __align__(256) __half g_bb16[(size_t)DOUT * RK];   // 2 MB
__device__ __align__(256) __half g_adt16[(size_t)DIN * RK];   // 2 MB

// ---------------------------------------------------------------------------
// PTX helpers (baseline ISA only)
// ---------------------------------------------------------------------------
__device__ __forceinline__ uint32_t smem_u32(const void* p) {
    uint32_t a;
    asm("{ .reg .u64 t; cvta.to.shared.u64 t, %1; cvt.u32.u64 %0, t; }" : "=r"(a) : "l"(p));
    return a;
}

#define CP_ASYNC16(dst, src) \
    asm volatile("cp.async.cg.shared.global [%0], [%1], 16;" :: "r"(dst), "l"(src) : "memory")
#define CP_ASYNC_COMMIT() asm volatile("cp.async.commit_group;" ::: "memory")
#define CP_ASYNC_WAIT(n)  asm volatile("cp.async.wait_group %0;" :: "n"(n) : "memory")

__device__ __forceinline__ void ldmatrix_x4(uint32_t* r, uint32_t addr) {
    asm volatile("ldmatrix.sync.aligned.m8n8.x4.shared.b16 {%0,%1,%2,%3}, [%4];"
                 : "=r"(r[0]), "=r"(r[1]), "=r"(r[2]), "=r"(r[3]) : "r"(addr));
}

__device__ __forceinline__ void mma16816(float* c, const uint32_t* a, const uint32_t* b) {
    asm volatile(
        "mma.sync.aligned.m16n8k16.row.col.f32.f16.f16.f32 "
        "{%0,%1,%2,%3}, {%4,%5,%6,%7}, {%8,%9}, {%0,%1,%2,%3};"
        : "+f"(c[0]), "+f"(c[1]), "+f"(c[2]), "+f"(c[3])
        : "r"(a[0]), "r"(a[1]), "r"(a[2]), "r"(a[3]), "r"(b[0]), "r"(b[1]));
}

__device__ __forceinline__ uint32_t swz(uint32_t off) {   // SW128
    return off ^ ((off >> 3) & 0x70);
}

// ---------------------------------------------------------------------------
// Conversion kernels
// ---------------------------------------------------------------------------
__global__ __launch_bounds__(256)
void conv_x_kernel(const float* __restrict__ x) {
    size_t i = ((size_t)blockIdx.x * blockDim.x + threadIdx.x) * 8;
    float4 a = *reinterpret_cast<const float4*>(x + i);
    float4 b = *reinterpret_cast<const float4*>(x + i + 4);
    float v[8] = {a.x, a.y, a.z, a.w, b.x, b.y, b.z, b.w};
    __align__(16) __half h[8];
    #pragma unroll
    for (int j = 0; j < 8; j++) h[j] = __float2half_rn(v[j]);
    *reinterpret_cast<uint4*>(&g_x16[i]) = *reinterpret_cast<uint4*>(h);
}

__global__ __launch_bounds__(256)
void conv_b_kernel(const float* __restrict__ Bm, const float* __restrict__ bvec) {
    size_t i = ((size_t)blockIdx.x * blockDim.x + threadIdx.x) * 8;
    const int o = (int)(i / RK);
    const float s = bvec[o];
    float4 a = *reinterpret_cast<const float4*>(Bm + i);
    float4 b = *reinterpret_cast<const float4*>(Bm + i + 4);
    float v[8] = {a.x, a.y, a.z, a.w, b.x, b.y, b.z, b.w};
    __align__(16) __half h[8];
    #pragma unroll
    for (int j = 0; j < 8; j++) h[j] = __float2half_rn(v[j] * s);
    *reinterpret_cast<uint4*>(&g_bb16[i]) = *reinterpret_cast<uint4*>(h);
}

__global__ __launch_bounds__(256)
void conv_adt_kernel(const float* __restrict__ A, const float* __restrict__ dvec) {
    __shared__ float tile[32][33];
    const int r0 = blockIdx.y * 32;
    const int i0 = blockIdx.x * 32;
    const int tx = threadIdx.x & 31;
    const int ty = threadIdx.x >> 5;
    #pragma unroll
    for (int t = 0; t < 4; t++) {
        const int r = ty + t * 8;
        tile[r][tx] = A[(size_t)(r0 + r) * DIN + i0 + tx] * dvec[r0 + r];
    }
    __syncthreads();
    #pragma unroll
    for (int t = 0; t < 4; t++) {
        const int i = ty + t * 8;
        g_adt16[(size_t)(i0 + i) * RK + r0 + tx] = __float2half_rn(tile[tx][i]);
    }
}

// ---------------------------------------------------------------------------
// NT-GEMM via mma.sync fp16. 256 threads (8 warps), warp tile 64x32,
// CTA tile 128x128, KC=64 (128 B rows, SW128), NSTAGE=3, 2 CTAs/SM,
// ONE sync per iteration.
//   FOLD=false: out[m][n] = sum_k x16[m][k]*w16[n][k] + bias[n]   (f32 out)
//   FOLD=true : w16[m][n] = fp16(W[m][n] + sum_k bb16[m][k]*adt16[n][k])
// ---------------------------------------------------------------------------
#define BM 128
#define BN 128
#define KC 64
#define A_BYTES (BM * 128)              // 16384
#define B_BYTES (BN * 128)              // 16384
#define STAGE_BYTES (A_BYTES + B_BYTES) // 32768
#define NSTAGE 3
#define SMEM_TOTAL (NSTAGE * STAGE_BYTES)  // 98304
#define NTHREADS 256

template<bool FOLD>
__device__ __forceinline__ void load_chunk(int chunk, uint32_t st, int tid,
                                           int m0, int n0) {
    const int KSTRIDE = FOLD ? RK : DIN;
    const __half* __restrict__ Aop = FOLD ? g_bb16 : g_x16;
    const __half* __restrict__ Bop = FOLD ? g_adt16 : g_w16;

    const int koff = chunk * KC;
    const int seg = tid & 7;        // 16B segment within 128B row
    const int rb  = tid >> 3;       // 0..31
    #pragma unroll
    for (int t = 0; t < 4; t++) {   // A: 128 rows
        const int r = t * 32 + rb;
        const __half* g = Aop + (size_t)(m0 + r) * KSTRIDE + koff + seg * 8;
        uint32_t off = r * 128 + seg * 16;
        CP_ASYNC16(st + swz(off), g);
    }
    #pragma unroll
    for (int t = 0; t < 4; t++) {   // B: 128 rows
        const int r = t * 32 + rb;
        const __half* g = Bop + (size_t)(n0 + r) * KSTRIDE + koff + seg * 8;
        uint32_t off = r * 128 + seg * 16;
        CP_ASYNC16(st + A_BYTES + swz(off), g);
    }
}

template<bool FOLD>
__global__ __launch_bounds__(NTHREADS, 2)
void gemm_tpl(const float* __restrict__ aux,   // bias (FOLD=0) or W (FOLD=1)
              float* __restrict__ outf) {      // main output (FOLD=0 only)
    const int NCHUNK = FOLD ? (RK / KC) : (DIN / KC);

    extern __shared__ char smem[];
    const uint32_t sb = smem_u32(smem);
    const int tid  = threadIdx.x;
    const int lane = tid & 31;
    const int wid  = tid >> 5;          // 0..7
    const int warp_m = wid & 1;         // 0..1 -> 64-row slab
    const int warp_n = wid >> 1;        // 0..3 -> 32-col slab

    const int n0 = blockIdx.x * BN;
    const int m0 = blockIdx.y * BM;

    float acc[4][4][4] = {};            // [mt][nt][4], warp tile 64x32

    const int arow = lane & 15;
    const int acol = (lane >> 4) * 8;
    const int brow = (lane & 7) + ((lane >> 4) << 3);
    const int bcol = ((lane >> 3) & 1) * 8;

    // Prologue: stages 0,1
    load_chunk<FOLD>(0, sb, tid, m0, n0);
    CP_ASYNC_COMMIT();
    load_chunk<FOLD>(1, sb + STAGE_BYTES, tid, m0, n0);
    CP_ASYNC_COMMIT();

    for (int i = 0; i < NCHUNK; i++) {
        const uint32_t st = sb + (i % NSTAGE) * STAGE_BYTES;

        if (i < NCHUNK - 1) { CP_ASYNC_WAIT(1); } else { CP_ASYNC_WAIT(0); }
        // Single barrier: publishes stage i AND guarantees all warps finished
        // computing stage i-1 — the stage the prefetch below overwrites
        // ((i+2)%3 == (i-1)%3).
        __syncthreads();

        if (i + 2 < NCHUNK) {
            load_chunk<FOLD>(i + 2, sb + ((i + 2) % NSTAGE) * STAGE_BYTES,
                             tid, m0, n0);
            CP_ASYNC_COMMIT();
        }

        #pragma unroll
        for (int ks = 0; ks < 4; ks++) {
            uint32_t a[4][4];
            #pragma unroll
            for (int mt = 0; mt < 4; mt++) {
                uint32_t off = (uint32_t)(warp_m * 64 + mt * 16 + arow) * 128
                             + (ks * 16 + acol) * 2;
                ldmatrix_x4(a[mt], st + swz(off));
            }
            uint32_t b[4][2];
            #pragma unroll
            for (int bg = 0; bg < 2; bg++) {
                uint32_t r[4];
                uint32_t off = (uint32_t)(warp_n * 32 + bg * 16 + brow) * 128
                             + (ks * 16 + bcol) * 2;
                ldmatrix_x4(r, st + A_BYTES + swz(off));
                b[bg * 2 + 0][0] = r[0]; b[bg * 2 + 0][1] = r[1];
                b[bg * 2 + 1][0] = r[2]; b[bg * 2 + 1][1] = r[3];
            }
            #pragma unroll
            for (int mt = 0; mt < 4; mt++)
                #pragma unroll
                for (int nt = 0; nt < 4; nt++)
                    mma16816(acc[mt][nt], a[mt], b[nt]);
        }
    }

    // Epilogue
    const int r0 = m0 + warp_m * 64 + (lane >> 2);
    const int c0 = n0 + warp_n * 32 + (lane & 3) * 2;
    #pragma unroll
    for (int mt = 0; mt < 4; mt++) {
        const int rm = r0 + mt * 16;
        #pragma unroll
        for (int nt = 0; nt < 4; nt++) {
            const int cb = c0 + nt * 8;
            if (FOLD) {
                const float2 w0 = *reinterpret_cast<const float2*>(&aux[(size_t)rm * DIN + cb]);
                const float2 w1 = *reinterpret_cast<const float2*>(&aux[(size_t)(rm + 8) * DIN + cb]);
                __half2 h0, h1;
                h0.x = __float2half_rn(w0.x + acc[mt][nt][0]);
                h0.y = __float2half_rn(w0.y + acc[mt][nt][1]);
                h1.x = __float2half_rn(w1.x + acc[mt][nt][2]);
                h1.y = __float2half_rn(w1.y + acc[mt][nt][3]);
                *reinterpret_cast<__half2*>(&g_w16[(size_t)rm * DIN + cb]) = h0;
                *reinterpret_cast<__half2*>(&g_w16[(size_t)(rm + 8) * DIN + cb]) = h1;
            } else {
                const float2 bb = *reinterpret_cast<const float2*>(&aux[cb]);
                float2 v0, v1;
                v0.x = acc[mt][nt][0] + bb.x;
                v0.y = acc[mt][nt][1] + bb.y;
                v1.x = acc[mt][nt][2] + bb.x;
                v1.y = acc[mt][nt][3] + bb.y;
                *reinterpret_cast<float2*>(&outf[(size_t)rm * DOUT + cb]) = v0;
                *reinterpret_cast<float2*>(&outf[(size_t)(rm + 8) * DOUT + cb]) = v1;
            }
        }
    }
}

// ---------------------------------------------------------------------------
// Harness entry. Inputs: x, W, bias, A_frozen, B_frozen, b_vec, d_vec.
// ---------------------------------------------------------------------------
extern "C" void kernel_launch(void* const* d_in, const int* in_sizes, int n_in,
                              void* d_out, int out_size) {
    const float* x    = (const float*)d_in[0];
    const float* W    = (const float*)d_in[1];
    const float* bias = (const float*)d_in[2];
    const float* A    = (const float*)d_in[3];
    const float* Bm   = (const float*)d_in[4];
    const float* bvec = (const float*)d_in[5];
    const float* dvec = (const float*)d_in[6];
    float* out = (float*)d_out;

    static int attr_set = 0;
    if (!attr_set) {
        cudaFuncSetAttribute(gemm_tpl<false>,
                             cudaFuncAttributeMaxDynamicSharedMemorySize, SMEM_TOTAL);
        cudaFuncSetAttribute(gemm_tpl<true>,
                             cudaFuncAttributeMaxDynamicSharedMemorySize, SMEM_TOTAL);
        attr_set = 1;
    }

    // fp16 conversions
    conv_x_kernel<<<(unsigned)((size_t)NN * DIN / 8 / 256), 256>>>(x);
    conv_b_kernel<<<(unsigned)((size_t)DOUT * RK / 8 / 256), 256>>>(Bm, bvec);
    {
        dim3 grid(DIN / 32, RK / 32);
        conv_adt_kernel<<<grid, 256>>>(A, dvec);
    }

    // Fold: w16 = fp16(W + bb16 @ adt16^T), K = RK
    {
        dim3 grid(DIN / BN, DOUT / BM);     // 32 x 32
        gemm_tpl<true><<<grid, NTHREADS, SMEM_TOTAL>>>(W, nullptr);
    }
    // Main GEMM: out = x16 @ w16^T + bias, K = DIN
    {
        dim3 grid(DOUT / BN, NN / BM);      // 32 x 64
        gemm_tpl<false><<<grid, NTHREADS, SMEM_TOTAL>>>(bias, out);
    }
}

// round 11
// speedup vs baseline: 1.3381x; 1.0318x over previous
#include <cuda_runtime.h>
#include <cuda_fp16.h>
#include <cstdint>

// Problem dims (fixed)
#define NN   8192
#define DIN  4096
#define DOUT 4096
#define RK   256

// ---------------------------------------------------------------------------
// Device scratch. Referenced ONLY from device code.
// ---------------------------------------------------------------------------
__device__ __align__(256) __half g_x16[(size_t)NN * DIN];     // 64 MB
__device__ __align__(256) __half g_w16[(size_t)DOUT * DIN];   // 32 MB
__device__ __align__(256) __half g_bb16[(size_t)DOUT * RK];   // 2 MB
__device__ __align__(256) __half g_adt16[(size_t)DIN * RK];   // 2 MB

// ---------------------------------------------------------------------------
// PTX helpers (baseline ISA only)
// ---------------------------------------------------------------------------
__device__ __forceinline__ uint32_t smem_u32(const void* p) {
    uint32_t a;
    asm("{ .reg .u64 t; cvta.to.shared.u64 t, %1; cvt.u32.u64 %0, t; }" : "=r"(a) : "l"(p));
    return a;
}

#define CP_ASYNC16(dst, src) \
    asm volatile("cp.async.cg.shared.global [%0], [%1], 16;" :: "r"(dst), "l"(src) : "memory")
#define CP_ASYNC_COMMIT() asm volatile("cp.async.commit_group;" ::: "memory")
#define CP_ASYNC_WAIT(n)  asm volatile("cp.async.wait_group %0;" :: "n"(n) : "memory")

__device__ __forceinline__ void ldmatrix_x4(uint32_t* r, uint32_t addr) {
    asm volatile("ldmatrix.sync.aligned.m8n8.x4.shared.b16 {%0,%1,%2,%3}, [%4];"
                 : "=r"(r[0]), "=r"(r[1]), "=r"(r[2]), "=r"(r[3]) : "r"(addr));
}

__device__ __forceinline__ void mma16816(float* c, const uint32_t* a, const uint32_t* b) {
    asm volatile(
        "mma.sync.aligned.m16n8k16.row.col.f32.f16.f16.f32 "
        "{%0,%1,%2,%3}, {%4,%5,%6,%7}, {%8,%9}, {%0,%1,%2,%3};"
        : "+f"(c[0]), "+f"(c[1]), "+f"(c[2]), "+f"(c[3])
        : "r"(a[0]), "r"(a[1]), "r"(a[2]), "r"(a[3]), "r"(b[0]), "r"(b[1]));
}

__device__ __forceinline__ uint32_t swz(uint32_t off) {   // SW128
    return off ^ ((off >> 3) & 0x70);
}

// ---------------------------------------------------------------------------
// Conversion kernels
// ---------------------------------------------------------------------------
__global__ __launch_bounds__(256)
void conv_x_kernel(const float* __restrict__ x) {
    size_t i = ((size_t)blockIdx.x * blockDim.x + threadIdx.x) * 8;
    float4 a = *reinterpret_cast<const float4*>(x + i);
    float4 b = *reinterpret_cast<const float4*>(x + i + 4);
    float v[8] = {a.x, a.y, a.z, a.w, b.x, b.y, b.z, b.w};
    __align__(16) __half h[8];
    #pragma unroll
    for (int j = 0; j < 8; j++) h[j] = __float2half_rn(v[j]);
    *reinterpret_cast<uint4*>(&g_x16[i]) = *reinterpret_cast<uint4*>(h);
}

__global__ __launch_bounds__(256)
void conv_b_kernel(const float* __restrict__ Bm, const float* __restrict__ bvec) {
    size_t i = ((size_t)blockIdx.x * blockDim.x + threadIdx.x) * 8;
    const int o = (int)(i / RK);
    const float s = bvec[o];
    float4 a = *reinterpret_cast<const float4*>(Bm + i);
    float4 b = *reinterpret_cast<const float4*>(Bm + i + 4);
    float v[8] = {a.x, a.y, a.z, a.w, b.x, b.y, b.z, b.w};
    __align__(16) __half h[8];
    #pragma unroll
    for (int j = 0; j < 8; j++) h[j] = __float2half_rn(v[j] * s);
    *reinterpret_cast<uint4*>(&g_bb16[i]) = *reinterpret_cast<uint4*>(h);
}

__global__ __launch_bounds__(256)
void conv_adt_kernel(const float* __restrict__ A, const float* __restrict__ dvec) {
    __shared__ float tile[32][33];
    const int r0 = blockIdx.y * 32;
    const int i0 = blockIdx.x * 32;
    const int tx = threadIdx.x & 31;
    const int ty = threadIdx.x >> 5;
    #pragma unroll
    for (int t = 0; t < 4; t++) {
        const int r = ty + t * 8;
        tile[r][tx] = A[(size_t)(r0 + r) * DIN + i0 + tx] * dvec[r0 + r];
    }
    __syncthreads();
    #pragma unroll
    for (int t = 0; t < 4; t++) {
        const int i = ty + t * 8;
        g_adt16[(size_t)(i0 + i) * RK + r0 + tx] = __float2half_rn(tile[tx][i]);
    }
}

// ---------------------------------------------------------------------------
// NT-GEMM via mma.sync fp16. 128 threads (4 warps), warp tile 64x64,
// CTA tile 128x128, KC=64 (128 B rows, SW128), NSTAGE=3, 2 CTAs/SM,
// ONE sync per iteration. Bigger warp tiles halve smem fragment re-reads
// (A and B each read by only 2 warps) -> balances the smem pipe vs HMMA.
//   FOLD=false: out[m][n] = sum_k x16[m][k]*w16[n][k] + bias[n]   (f32 out)
//   FOLD=true : w16[m][n] = fp16(W[m][n] + sum_k bb16[m][k]*adt16[n][k])
// ---------------------------------------------------------------------------
#define BM 128
#define BN 128
#define KC 64
#define A_BYTES (BM * 128)              // 16384
#define B_BYTES (BN * 128)              // 16384
#define STAGE_BYTES (A_BYTES + B_BYTES) // 32768
#define NSTAGE 3
#define SMEM_TOTAL (NSTAGE * STAGE_BYTES)  // 98304
#define NTHREADS 128

template<bool FOLD>
__device__ __forceinline__ void load_chunk(int chunk, uint32_t st, int tid,
                                           int m0, int n0) {
    const int KSTRIDE = FOLD ? RK : DIN;
    const __half* __restrict__ Aop = FOLD ? g_bb16 : g_x16;
    const __half* __restrict__ Bop = FOLD ? g_adt16 : g_w16;

    const int koff = chunk * KC;
    const int seg = tid & 7;        // 16B segment within 128B row
    const int rb  = tid >> 3;       // 0..15
    #pragma unroll
    for (int t = 0; t < 8; t++) {   // A: 128 rows
        const int r = t * 16 + rb;
        const __half* g = Aop + (size_t)(m0 + r) * KSTRIDE + koff + seg * 8;
        uint32_t off = r * 128 + seg * 16;
        CP_ASYNC16(st + swz(off), g);
    }
    #pragma unroll
    for (int t = 0; t < 8; t++) {   // B: 128 rows
        const int r = t * 16 + rb;
        const __half* g = Bop + (size_t)(n0 + r) * KSTRIDE + koff + seg * 8;
        uint32_t off = r * 128 + seg * 16;
        CP_ASYNC16(st + A_BYTES + swz(off), g);
    }
}

template<bool FOLD>
__global__ __launch_bounds__(NTHREADS, 2)
void gemm_tpl(const float* __restrict__ aux,   // bias (FOLD=0) or W (FOLD=1)
              float* __restrict__ outf) {      // main output (FOLD=0 only)
    const int NCHUNK = FOLD ? (RK / KC) : (DIN / KC);

    extern __shared__ char smem[];
    const uint32_t sb = smem_u32(smem);
    const int tid  = threadIdx.x;
    const int lane = tid & 31;
    const int wid  = tid >> 5;          // 0..3
    const int warp_m = wid & 1;         // 0..1 -> 64-row slab
    const int warp_n = wid >> 1;        // 0..1 -> 64-col slab

    const int n0 = blockIdx.x * BN;
    const int m0 = blockIdx.y * BM;

    float acc[4][8][4] = {};            // [mt][nt][4], warp tile 64x64 -> 128 regs

    const int arow = lane & 15;
    const int acol = (lane >> 4) * 8;
    const int brow = (lane & 7) + ((lane >> 4) << 3);
    const int bcol = ((lane >> 3) & 1) * 8;

    // Prologue: stages 0,1
    load_chunk<FOLD>(0, sb, tid, m0, n0);
    CP_ASYNC_COMMIT();
    load_chunk<FOLD>(1, sb + STAGE_BYTES, tid, m0, n0);
    CP_ASYNC_COMMIT();

    for (int i = 0; i < NCHUNK; i++) {
        const uint32_t st = sb + (i % NSTAGE) * STAGE_BYTES;

        if (i < NCHUNK - 1) { CP_ASYNC_WAIT(1); } else { CP_ASYNC_WAIT(0); }
        // Single barrier: publishes stage i AND guarantees all warps finished
        // computing stage i-1 — the stage the prefetch below overwrites.
        __syncthreads();

        if (i + 2 < NCHUNK) {
            load_chunk<FOLD>(i + 2, sb + ((i + 2) % NSTAGE) * STAGE_BYTES,
                             tid, m0, n0);
            CP_ASYNC_COMMIT();
        }

        #pragma unroll
        for (int ks = 0; ks < 4; ks++) {
            uint32_t a[4][4];
            #pragma unroll
            for (int mt = 0; mt < 4; mt++) {
                uint32_t off = (uint32_t)(warp_m * 64 + mt * 16 + arow) * 128
                             + (ks * 16 + acol) * 2;
                ldmatrix_x4(a[mt], st + swz(off));
            }
            uint32_t b[8][2];
            #pragma unroll
            for (int bg = 0; bg < 4; bg++) {
                uint32_t r[4];
                uint32_t off = (uint32_t)(warp_n * 64 + bg * 16 + brow) * 128
                             + (ks * 16 + bcol) * 2;
                ldmatrix_x4(r, st + A_BYTES + swz(off));
                b[bg * 2 + 0][0] = r[0]; b[bg * 2 + 0][1] = r[1];
                b[bg * 2 + 1][0] = r[2]; b[bg * 2 + 1][1] = r[3];
            }
            #pragma unroll
            for (int mt = 0; mt < 4; mt++)
                #pragma unroll
                for (int nt = 0; nt < 8; nt++)
                    mma16816(acc[mt][nt], a[mt], b[nt]);
        }
    }

    // Epilogue
    const int r0 = m0 + warp_m * 64 + (lane >> 2);
    const int c0 = n0 + warp_n * 64 + (lane & 3) * 2;
    #pragma unroll
    for (int mt = 0; mt < 4; mt++) {
        const int rm = r0 + mt * 16;
        #pragma unroll
        for (int nt = 0; nt < 8; nt++) {
            const int cb = c0 + nt * 8;
            if (FOLD) {
                const float2 w0 = *reinterpret_cast<const float2*>(&aux[(size_t)rm * DIN + cb]);
                const float2 w1 = *reinterpret_cast<const float2*>(&aux[(size_t)(rm + 8) * DIN + cb]);
                __half2 h0, h1;
                h0.x = __float2half_rn(w0.x + acc[mt][nt][0]);
                h0.y = __float2half_rn(w0.y + acc[mt][nt][1]);
                h1.x = __float2half_rn(w1.x + acc[mt][nt][2]);
                h1.y = __float2half_rn(w1.y + acc[mt][nt][3]);
                *reinterpret_cast<__half2*>(&g_w16[(size_t)rm * DIN + cb]) = h0;
                *reinterpret_cast<__half2*>(&g_w16[(size_t)(rm + 8) * DIN + cb]) = h1;
            } else {
                const float2 bb = *reinterpret_cast<const float2*>(&aux[cb]);
                float2 v0, v1;
                v0.x = acc[mt][nt][0] + bb.x;
                v0.y = acc[mt][nt][1] + bb.y;
                v1.x = acc[mt][nt][2] + bb.x;
                v1.y = acc[mt][nt][3] + bb.y;
                *reinterpret_cast<float2*>(&outf[(size_t)rm * DOUT + cb]) = v0;
                *reinterpret_cast<float2*>(&outf[(size_t)(rm + 8) * DOUT + cb]) = v1;
            }
        }
    }
}

// ---------------------------------------------------------------------------
// Harness entry. Inputs: x, W, bias, A_frozen, B_frozen, b_vec, d_vec.
// ---------------------------------------------------------------------------
extern "C" void kernel_launch(void* const* d_in, const int* in_sizes, int n_in,
                              void* d_out, int out_size) {
    const float* x    = (const float*)d_in[0];
    const float* W    = (const float*)d_in[1];
    const float* bias = (const float*)d_in[2];
    const float* A    = (const float*)d_in[3];
    const float* Bm   = (const float*)d_in[4];
    const float* bvec = (const float*)d_in[5];
    const float* dvec = (const float*)d_in[6];
    float* out = (float*)d_out;

    static int attr_set = 0;
    if (!attr_set) {
        cudaFuncSetAttribute(gemm_tpl<false>,
                             cudaFuncAttributeMaxDynamicSharedMemorySize, SMEM_TOTAL);
        cudaFuncSetAttribute(gemm_tpl<true>,
                             cudaFuncAttributeMaxDynamicSharedMemorySize, SMEM_TOTAL);
        attr_set = 1;
    }

    // fp16 conversions
    conv_x_kernel<<<(unsigned)((size_t)NN * DIN / 8 / 256), 256>>>(x);
    conv_b_kernel<<<(unsigned)((size_t)DOUT * RK / 8 / 256), 256>>>(Bm, bvec);
    {
        dim3 grid(DIN / 32, RK / 32);
        conv_adt_kernel<<<grid, 256>>>(A, dvec);
    }

    // Fold: w16 = fp16(W + bb16 @ adt16^T), K = RK
    {
        dim3 grid(DIN / BN, DOUT / BM);     // 32 x 32
        gemm_tpl<true><<<grid, NTHREADS, SMEM_TOTAL>>>(W, nullptr);
    }
    // Main GEMM: out = x16 @ w16^T + bias, K = DIN
    {
        dim3 grid(DOUT / BN, NN / BM);      // 32 x 64
        gemm_tpl<false><<<grid, NTHREADS, SMEM_TOTAL>>>(bias, out);
    }
}